// round 1
// baseline (speedup 1.0000x reference)
#include <cuda_runtime.h>
#include <cuda_bf16.h>
#include <cstdint>

// Problem constants
#define BB   4
#define HH   16
#define SKK  4096
#define SQQ  4096
#define DD   64
#define NN   32
#define SPLIT 8
#define KEYS_PER_BLOCK (SKK / SPLIT)   // 512
#define CHUNK 32

// Scratch (static device arrays; no allocations anywhere)
__device__ float g_part[SPLIT * 64 * 64 * DD];  // [split][hb][f(64)][d]  = 8 MB
__device__ float g_ab[64 * 64 * DD];            // [hb][f(64)][d]         = 1 MB

// ---- packed f32x2 helpers (Blackwell fma pipe, 2 FMA per slot) ----
__device__ __forceinline__ unsigned long long pack2(float lo, float hi) {
    unsigned long long r;
    asm("mov.b64 %0, {%1, %2};" : "=l"(r) : "f"(lo), "f"(hi));
    return r;
}
__device__ __forceinline__ void unpack2(unsigned long long v, float& lo, float& hi) {
    asm("mov.b64 {%0, %1}, %2;" : "=f"(lo), "=f"(hi) : "l"(v));
}
__device__ __forceinline__ unsigned long long ffma2(unsigned long long a,
                                                    unsigned long long b,
                                                    unsigned long long c) {
    unsigned long long d;
    asm("fma.rn.f32x2 %0, %1, %2, %3;" : "=l"(d) : "l"(a), "l"(b), "l"(c));
    return d;
}
__device__ __forceinline__ unsigned long long lds64(const float* p) {
    return *reinterpret_cast<const unsigned long long*>(p);
}

// freqs[n] = (n/(N-1)) * N * pi
__device__ __forceinline__ float FREQ(int n) {
    return (float)n * (32.0f * 3.14159265358979323846f / 31.0f);
}

// ============================================================================
// Kernel 1: partial KV = [cos_k^T V ; sin_k^T V] over an SK slice.
// grid: (SPLIT, 64 hb), block 256.
// Thread owns one n (32) and 8 d's (8 groups) -> 16 fp32 accumulators (8 f32x2).
// ============================================================================
__global__ __launch_bounds__(256) void kv_partial(const float* __restrict__ key,
                                                  const float* __restrict__ value) {
    const int s  = blockIdx.x;
    const int hb = blockIdx.y;
    const int h  = hb >> 2;          // hb = h*4 + b
    const int b  = hb & 3;
    const int tid = threadIdx.x;

    __shared__ float skey[CHUNK];
    __shared__ float sv[CHUNK][DD];
    __shared__ float scs[2][CHUNK][NN];  // [cos|sin][k][n]

    const int n  = tid >> 3;   // 0..31
    const int dg = tid & 7;    // 0..7
    const int d0 = dg * 8;

    unsigned long long accC[4] = {0ull, 0ull, 0ull, 0ull};
    unsigned long long accS[4] = {0ull, 0ull, 0ull, 0ull};

    const int kbase = s * KEYS_PER_BLOCK;

    for (int c = 0; c < KEYS_PER_BLOCK / CHUNK; c++) {
        __syncthreads();  // previous iteration's FMA reads done
        const int kk0 = kbase + c * CHUNK;

        // stage keys + value rows
        if (tid < CHUNK)
            skey[tid] = key[((size_t)b * SKK + kk0 + tid) * HH + h];
        #pragma unroll
        for (int i = 0; i < 2; i++) {
            int idx4 = i * 256 + tid;           // 0..511
            int k = idx4 >> 4, j = idx4 & 15;
            const float4* gp = reinterpret_cast<const float4*>(
                value + ((size_t)b * SKK + kk0 + k) * (HH * DD) + h * DD) + j;
            reinterpret_cast<float4*>(&sv[k][0])[j] = *gp;
        }
        __syncthreads();

        // trig table for this chunk: 32k x 32n, 4 sincos per thread
        #pragma unroll
        for (int i = 0; i < 4; i++) {
            int idx = i * 256 + tid;            // 0..1023
            int k = idx >> 5, nn = idx & 31;
            float sres, cres;
            sincosf(FREQ(nn) * skey[k], &sres, &cres);
            scs[0][k][nn] = cres;
            scs[1][k][nn] = sres;
        }
        __syncthreads();

        // rank-1 accumulation over the chunk
        #pragma unroll 4
        for (int k = 0; k < CHUNK; k++) {
            float cv = scs[0][k][n];
            float sn = scs[1][k][n];
            unsigned long long c2 = pack2(cv, cv);
            unsigned long long s2 = pack2(sn, sn);
            #pragma unroll
            for (int j = 0; j < 4; j++) {
                unsigned long long v2 = lds64(&sv[k][d0 + 2 * j]);
                accC[j] = ffma2(c2, v2, accC[j]);
                accS[j] = ffma2(s2, v2, accS[j]);
            }
        }
    }

    // write partials: cos rows at f=n, sin rows at f=32+n
    float oc[8], os[8];
    #pragma unroll
    for (int j = 0; j < 4; j++) {
        unpack2(accC[j], oc[2 * j], oc[2 * j + 1]);
        unpack2(accS[j], os[2 * j], os[2 * j + 1]);
    }
    float* pc = g_part + ((size_t)(s * 64 + hb) * 64 + n) * DD + d0;
    float* ps = g_part + ((size_t)(s * 64 + hb) * 64 + 32 + n) * DD + d0;
    reinterpret_cast<float4*>(pc)[0] = make_float4(oc[0], oc[1], oc[2], oc[3]);
    reinterpret_cast<float4*>(pc)[1] = make_float4(oc[4], oc[5], oc[6], oc[7]);
    reinterpret_cast<float4*>(ps)[0] = make_float4(os[0], os[1], os[2], os[3]);
    reinterpret_cast<float4*>(ps)[1] = make_float4(os[4], os[5], os[6], os[7]);
}

// ============================================================================
// Kernel 2: reduce split partials and fold amplitudes:
//   A[n][d] = ra*KC - ia*KS   (rows 0..31)
//   B[n][d] = ra*KS + ia*KC   (rows 32..63)
// grid: 64 blocks (one per hb), block 256.
// ============================================================================
__global__ __launch_bounds__(256) void kv_combine(const float* __restrict__ ra,
                                                  const float* __restrict__ ia) {
    const int hb = blockIdx.x;
    const int h  = hb >> 2;
    const int tid = threadIdx.x;

    #pragma unroll
    for (int i = 0; i < 8; i++) {
        int idx = i * 256 + tid;          // 0..2047 -> (n,d)
        int n = idx >> 6, d = idx & 63;
        float sc = 0.f, ss = 0.f;
        #pragma unroll
        for (int s = 0; s < SPLIT; s++) {
            const float* base = g_part + (size_t)(s * 64 + hb) * 64 * DD;
            sc += base[n * DD + d];
            ss += base[(32 + n) * DD + d];
        }
        float r  = ra[h * NN + n];
        float im = ia[h * NN + n];
        g_ab[((size_t)hb * 64 + n) * DD + d]      = r * sc - im * ss;
        g_ab[((size_t)hb * 64 + 32 + n) * DD + d] = r * ss + im * sc;
    }
}

// ============================================================================
// Kernel 3: out[q][d] = sum_f trig_q[q][f] * AB[f][d], 64-query tiles.
// grid: (SQ/64, 64 hb), block 256. Per thread: 4 q x 4 d (2 f32x2 each).
// ============================================================================
__global__ __launch_bounds__(256) void phase2(const float* __restrict__ query,
                                              float* __restrict__ out) {
    const int qt = blockIdx.x;
    const int hb = blockIdx.y;
    const int h  = hb >> 2;
    const int b  = hb & 3;
    const int tid = threadIdx.x;
    const int q0 = qt * 64;

    __shared__ float sAB[64 * DD];       // 16 KB
    __shared__ float strig[64][64];      // 16 KB  (cos at [q][n], sin at [q][32+n])

    // load A/B tile (L2-resident, 1 MB total across grid)
    #pragma unroll
    for (int i = 0; i < 4; i++) {
        int idx4 = i * 256 + tid;        // 0..1023
        reinterpret_cast<float4*>(sAB)[idx4] =
            reinterpret_cast<const float4*>(g_ab + (size_t)hb * 64 * DD)[idx4];
    }

    // trig tile: 64 q x 32 n, 8 sincos per thread
    #pragma unroll
    for (int i = 0; i < 8; i++) {
        int idx = i * 256 + tid;         // 0..2047
        int q = idx >> 5, n = idx & 31;
        float qv = query[((size_t)b * SQQ + q0 + q) * HH + h];
        float sres, cres;
        sincosf(FREQ(n) * qv, &sres, &cres);
        strig[q][n]      = cres;
        strig[q][32 + n] = sres;
    }
    __syncthreads();

    const int dp = tid & 15;   int d0 = dp * 4;
    const int qg = tid >> 4;   int ql = qg * 4;

    unsigned long long acc[4][2] = {};
    #pragma unroll 8
    for (int f = 0; f < 64; f++) {
        unsigned long long a0 = lds64(&sAB[f * DD + d0]);
        unsigned long long a1 = lds64(&sAB[f * DD + d0 + 2]);
        #pragma unroll
        for (int qi = 0; qi < 4; qi++) {
            float t = strig[ql + qi][f];
            unsigned long long t2 = pack2(t, t);
            acc[qi][0] = ffma2(t2, a0, acc[qi][0]);
            acc[qi][1] = ffma2(t2, a1, acc[qi][1]);
        }
    }

    #pragma unroll
    for (int qi = 0; qi < 4; qi++) {
        float4 o;
        unpack2(acc[qi][0], o.x, o.y);
        unpack2(acc[qi][1], o.z, o.w);
        *reinterpret_cast<float4*>(
            out + (((size_t)b * SQQ + q0 + ql + qi) * HH + h) * DD + d0) = o;
    }
}

// ============================================================================
extern "C" void kernel_launch(void* const* d_in, const int* in_sizes, int n_in,
                              void* d_out, int out_size) {
    const float* key   = (const float*)d_in[0];  // (B, SK, H)
    const float* value = (const float*)d_in[1];  // (B, SK, H*D)
    const float* query = (const float*)d_in[2];  // (B, SQ, H)
    const float* ra    = (const float*)d_in[3];  // (H,1,1,N)
    const float* ia    = (const float*)d_in[4];  // (H,1,1,N)
    float* out = (float*)d_out;                  // (B, SQ, H*D)

    dim3 g1(SPLIT, 64);
    kv_partial<<<g1, 256>>>(key, value);
    kv_combine<<<64, 256>>>(ra, ia);
    dim3 g3(SQQ / 64, 64);
    phase2<<<g3, 256>>>(query, out);
}

// round 2
// speedup vs baseline: 2.6793x; 2.6793x over previous
#include <cuda_runtime.h>
#include <cuda_bf16.h>
#include <cstdint>

// Problem constants
#define BB   4
#define HH   16
#define SKK  4096
#define SQQ  4096
#define DD   64
#define NN   32
#define SPLIT_BLK 8
#define SPLIT 16                       // 2 substreams per block
#define KEYS_PER_BLOCK (SKK / SPLIT_BLK)   // 512
#define CHUNK 32
#define SVPAD 68                       // padded row: 68 floats = 272B (16B aligned)

typedef unsigned long long u64;

// Scratch (static device arrays; no allocations anywhere)
__device__ float g_part[SPLIT * 64 * 64 * DD];  // [split][hb][f(64)][d] = 16.8 MB
__device__ float g_ab[64 * 64 * DD];            // [hb][f(64)][d]        = 1 MB

// ---- packed f32x2 helpers ----
__device__ __forceinline__ u64 pack2(float lo, float hi) {
    u64 r; asm("mov.b64 %0, {%1, %2};" : "=l"(r) : "f"(lo), "f"(hi)); return r;
}
__device__ __forceinline__ void unpack2(u64 v, float& lo, float& hi) {
    asm("mov.b64 {%0, %1}, %2;" : "=f"(lo), "=f"(hi) : "l"(v));
}
__device__ __forceinline__ u64 ffma2(u64 a, u64 b, u64 c) {
    u64 d; asm("fma.rn.f32x2 %0, %1, %2, %3;" : "=l"(d) : "l"(a), "l"(b), "l"(c));
    return d;
}
__device__ __forceinline__ u64 lds64(const float* p) {
    return *reinterpret_cast<const u64*>(p);
}

__device__ __forceinline__ float FREQ(int n) {
    return (float)n * (32.0f * 3.14159265358979323846f / 31.0f);
}

// ============================================================================
// Kernel 1: partial KV = [cos_k^T V ; sin_k^T V] over an SK slice.
// grid: (8, 64 hb), block 256 (two 128-thread k-substreams).
// Thread tile: 2 n (n0, n0+16) x 8 d (d0..d0+3, d0+32..d0+35).
// ============================================================================
__global__ __launch_bounds__(256) void kv_partial(const float* __restrict__ key,
                                                  const float* __restrict__ value) {
    const int sblk = blockIdx.x;
    const int hb = blockIdx.y;
    const int h  = hb >> 2;
    const int b  = hb & 3;
    const int tid = threadIdx.x;
    const int ss = tid >> 7;          // substream 0/1
    const int t  = tid & 127;
    const int n0 = t >> 3;            // 0..15  (n values n0, n0+16)
    const int dg = t & 7;
    const int d0 = dg * 4;            // d values d0..d0+3 and d0+32..d0+35

    __shared__ float sv[CHUNK][SVPAD];     // value rows (d<64 used)
    __shared__ float2 scs[CHUNK][NN];      // {cos,sin}[k][n]

    u64 aC0[4] = {}, aS0[4] = {}, aC1[4] = {}, aS1[4] = {};

    const int kbase = sblk * KEYS_PER_BLOCK;
    const size_t vrow_base = ((size_t)b * SKK) * (HH * DD) + (size_t)h * DD;
    const size_t krow_base = (size_t)b * SKK * HH + h;

    for (int c = 0; c < KEYS_PER_BLOCK / CHUNK; c++) {
        __syncthreads();
        const int kk0 = kbase + c * CHUNK;

        // stage value rows (32 rows x 16 float4)
        #pragma unroll
        for (int i = 0; i < 2; i++) {
            int idx4 = i * 256 + tid;
            int k = idx4 >> 4, j = idx4 & 15;
            const float4* gp = reinterpret_cast<const float4*>(
                value + vrow_base + (size_t)(kk0 + k) * (HH * DD)) + j;
            *reinterpret_cast<float4*>(&sv[k][j * 4]) = *gp;
        }
        // trig table: key read straight from gmem (L1 broadcast)
        #pragma unroll
        for (int i = 0; i < 4; i++) {
            int idx = i * 256 + tid;
            int k = idx >> 5, nn = idx & 31;
            float kv = key[krow_base + (size_t)(kk0 + k) * HH];
            float sres, cres;
            sincosf(FREQ(nn) * kv, &sres, &cres);
            scs[k][nn] = make_float2(cres, sres);
        }
        __syncthreads();

        const int kb = ss * 16;
        #pragma unroll
        for (int kk = 0; kk < 16; kk++) {
            const float* vrow = &sv[kb + kk][0];
            float2 t0 = scs[kb + kk][n0];
            float2 t1 = scs[kb + kk][n0 + 16];
            u64 v0 = lds64(vrow + d0);
            u64 v1 = lds64(vrow + d0 + 2);
            u64 v2 = lds64(vrow + d0 + 32);
            u64 v3 = lds64(vrow + d0 + 34);
            u64 c0 = pack2(t0.x, t0.x), s0 = pack2(t0.y, t0.y);
            u64 c1 = pack2(t1.x, t1.x), s1 = pack2(t1.y, t1.y);
            aC0[0] = ffma2(c0, v0, aC0[0]); aC0[1] = ffma2(c0, v1, aC0[1]);
            aC0[2] = ffma2(c0, v2, aC0[2]); aC0[3] = ffma2(c0, v3, aC0[3]);
            aS0[0] = ffma2(s0, v0, aS0[0]); aS0[1] = ffma2(s0, v1, aS0[1]);
            aS0[2] = ffma2(s0, v2, aS0[2]); aS0[3] = ffma2(s0, v3, aS0[3]);
            aC1[0] = ffma2(c1, v0, aC1[0]); aC1[1] = ffma2(c1, v1, aC1[1]);
            aC1[2] = ffma2(c1, v2, aC1[2]); aC1[3] = ffma2(c1, v3, aC1[3]);
            aS1[0] = ffma2(s1, v0, aS1[0]); aS1[1] = ffma2(s1, v1, aS1[1]);
            aS1[2] = ffma2(s1, v2, aS1[2]); aS1[3] = ffma2(s1, v3, aS1[3]);
        }
    }

    // write partials: split index = sblk*2 + ss
    const int sout = sblk * 2 + ss;
    float* base = g_part + (size_t)(sout * 64 + hb) * 64 * DD;
    float o[8];
    u64* accs[4] = {aC0, aC1, aS0, aS1};
    const int frow[4] = {n0, n0 + 16, 32 + n0, 48 + n0};
    #pragma unroll
    for (int g = 0; g < 4; g++) {
        #pragma unroll
        for (int j = 0; j < 4; j++) unpack2(accs[g][j], o[2 * j], o[2 * j + 1]);
        float* p = base + frow[g] * DD + d0;
        *reinterpret_cast<float4*>(p)      = make_float4(o[0], o[1], o[2], o[3]);
        *reinterpret_cast<float4*>(p + 32) = make_float4(o[4], o[5], o[6], o[7]);
    }
}

// ============================================================================
// Kernel 2: reduce split partials and fold amplitudes:
//   A[n][d] = ra*KC - ia*KS ;  B[n][d] = ra*KS + ia*KC
// ============================================================================
__global__ __launch_bounds__(256) void kv_combine(const float* __restrict__ ra,
                                                  const float* __restrict__ ia) {
    const int hb = blockIdx.x;
    const int h  = hb >> 2;
    const int tid = threadIdx.x;

    #pragma unroll
    for (int i = 0; i < 8; i++) {
        int idx = i * 256 + tid;          // (n,d)
        int n = idx >> 6, d = idx & 63;
        float sc = 0.f, ss = 0.f;
        #pragma unroll
        for (int s = 0; s < SPLIT; s++) {
            const float* base = g_part + (size_t)(s * 64 + hb) * 64 * DD;
            sc += base[n * DD + d];
            ss += base[(32 + n) * DD + d];
        }
        float r  = ra[h * NN + n];
        float im = ia[h * NN + n];
        g_ab[((size_t)hb * 64 + n) * DD + d]      = r * sc - im * ss;
        g_ab[((size_t)hb * 64 + 32 + n) * DD + d] = r * ss + im * sc;
    }
}

// ============================================================================
// Kernel 3: out[q][d] = sum_n cos_q*A[n][d] + sin_q*B[n][d].
// grid: (SQ/128, 64 hb), block 256. Thread tile: 4 q x 8 d.
// ============================================================================
__global__ __launch_bounds__(256) void phase2(const float* __restrict__ query,
                                              float* __restrict__ out) {
    const int qt = blockIdx.x;
    const int hb = blockIdx.y;
    const int h  = hb >> 2;
    const int b  = hb & 3;
    const int tid = threadIdx.x;
    const int qblk = qt * 128;

    __shared__ float sAB[64][SVPAD];       // A rows 0..31, B rows 32..63
    __shared__ float2 strig[NN][128];      // [n][q] {cos,sin}  32KB

    // load A/B tile
    #pragma unroll
    for (int i = 0; i < 4; i++) {
        int idx4 = i * 256 + tid;          // 0..1023: 64 rows x 16 float4
        int f = idx4 >> 4, j = idx4 & 15;
        *reinterpret_cast<float4*>(&sAB[f][j * 4]) =
            reinterpret_cast<const float4*>(g_ab + (size_t)hb * 64 * DD)[idx4];
    }
    // trig tile: 128 q x 32 n
    #pragma unroll
    for (int i = 0; i < 16; i++) {
        int idx = i * 256 + tid;           // 0..4095
        int n = idx >> 7, q = idx & 127;
        float qv = query[((size_t)b * SQQ + qblk + q) * HH + h];
        float sres, cres;
        sincosf(FREQ(n) * qv, &sres, &cres);
        strig[n][q] = make_float2(cres, sres);
    }
    __syncthreads();

    const int qg = tid >> 3;   const int q0 = qg * 4;   // 4 q
    const int dg = tid & 7;    const int d0 = dg * 4;   // 8 d (two windows)

    u64 acc[4][4] = {};
    #pragma unroll 4
    for (int n = 0; n < NN; n++) {
        const float* arow = &sAB[n][0];
        const float* brow = &sAB[32 + n][0];
        u64 a0 = lds64(arow + d0),      a1 = lds64(arow + d0 + 2);
        u64 a2 = lds64(arow + d0 + 32), a3 = lds64(arow + d0 + 34);
        u64 b0 = lds64(brow + d0),      b1 = lds64(brow + d0 + 2);
        u64 b2 = lds64(brow + d0 + 32), b3 = lds64(brow + d0 + 34);
        #pragma unroll
        for (int qi = 0; qi < 4; qi++) {
            float2 t = strig[n][q0 + qi];
            u64 cq = pack2(t.x, t.x);
            u64 sq = pack2(t.y, t.y);
            acc[qi][0] = ffma2(cq, a0, acc[qi][0]);
            acc[qi][1] = ffma2(cq, a1, acc[qi][1]);
            acc[qi][2] = ffma2(cq, a2, acc[qi][2]);
            acc[qi][3] = ffma2(cq, a3, acc[qi][3]);
            acc[qi][0] = ffma2(sq, b0, acc[qi][0]);
            acc[qi][1] = ffma2(sq, b1, acc[qi][1]);
            acc[qi][2] = ffma2(sq, b2, acc[qi][2]);
            acc[qi][3] = ffma2(sq, b3, acc[qi][3]);
        }
    }

    #pragma unroll
    for (int qi = 0; qi < 4; qi++) {
        float o[8];
        #pragma unroll
        for (int j = 0; j < 4; j++) unpack2(acc[qi][j], o[2 * j], o[2 * j + 1]);
        float* p = out + (((size_t)b * SQQ + qblk + q0 + qi) * HH + h) * DD + d0;
        *reinterpret_cast<float4*>(p)      = make_float4(o[0], o[1], o[2], o[3]);
        *reinterpret_cast<float4*>(p + 32) = make_float4(o[4], o[5], o[6], o[7]);
    }
}

// ============================================================================
extern "C" void kernel_launch(void* const* d_in, const int* in_sizes, int n_in,
                              void* d_out, int out_size) {
    const float* key   = (const float*)d_in[0];  // (B, SK, H)
    const float* value = (const float*)d_in[1];  // (B, SK, H*D)
    const float* query = (const float*)d_in[2];  // (B, SQ, H)
    const float* ra    = (const float*)d_in[3];  // (H,1,1,N)
    const float* ia    = (const float*)d_in[4];  // (H,1,1,N)
    float* out = (float*)d_out;                  // (B, SQ, H*D)

    dim3 g1(SPLIT_BLK, 64);
    kv_partial<<<g1, 256>>>(key, value);
    kv_combine<<<64, 256>>>(ra, ia);
    dim3 g3(SQQ / 128, 64);
    phase2<<<g3, 256>>>(query, out);
}

// round 3
// speedup vs baseline: 2.8678x; 1.0704x over previous
#include <cuda_runtime.h>
#include <cuda_bf16.h>
#include <cstdint>

#define BB   4
#define HH   16
#define SKK  4096
#define SQQ  4096
#define DD   64
#define NN   32
#define SPLIT 8
#define KEYS_PER_BLOCK (SKK / SPLIT)   // 512
#define CHUNK 32
#define WOM  3.241592653589793f        // placeholder (not used)

typedef unsigned long long u64;

// omega = 32*pi/31
__device__ __forceinline__ float OMEGA() { return 32.0f * 3.14159265358979323846f / 31.0f; }

// Scratch
__device__ float g_part[SPLIT * 64 * 64 * DD];  // [split][hb][f(64)][d] = 8 MB
__device__ float g_ab[64 * 64 * DD];            // [hb][f(64)][d]        = 1 MB

// ---- packed f32x2 helpers ----
__device__ __forceinline__ u64 pack2(float lo, float hi) {
    u64 r; asm("mov.b64 %0, {%1, %2};" : "=l"(r) : "f"(lo), "f"(hi)); return r;
}
__device__ __forceinline__ void unpack2(u64 v, float& lo, float& hi) {
    asm("mov.b64 {%0, %1}, %2;" : "=f"(lo), "=f"(hi) : "l"(v));
}
__device__ __forceinline__ u64 ffma2(u64 a, u64 b, u64 c) {
    u64 d; asm("fma.rn.f32x2 %0, %1, %2, %3;" : "=l"(d) : "l"(a), "l"(b), "l"(c));
    return d;
}
__device__ __forceinline__ u64 lds64(const float* p) {
    return *reinterpret_cast<const u64*>(p);
}

// ============================================================================
// Kernel 1: partial KV = [cos_k^T V ; sin_k^T V] over an SK slice.
// grid: (8, 64 hb), block 256 = 4 substreams x 64 threads.
// Thread tile: 4 n (n0+8i) x 8 d (d0..d0+3, d0+32..d0+35).
// ============================================================================
__global__ __launch_bounds__(256, 2) void kv_partial(const float* __restrict__ key,
                                                     const float* __restrict__ value) {
    const int sblk = blockIdx.x;
    const int hb = blockIdx.y;
    const int h  = hb >> 2;
    const int b  = hb & 3;
    const int tid = threadIdx.x;
    const int ss = tid >> 6;          // substream 0..3 (8 k each per chunk)
    const int t  = tid & 63;
    const int n0 = t >> 3;            // 0..7
    const int dg = t & 7;
    const int d0 = dg * 4;

    __shared__ float  sv[CHUNK][68];       // value rows, padded
    __shared__ float2 scs[CHUNK][NN + 1];  // {cos,sin}[k][n], padded
    __shared__ float  red[64][68];         // cross-substream reduction buffer

    u64 acc[2][4][4];                      // [cos/sin][n-idx][d-pair]
    #pragma unroll
    for (int a = 0; a < 2; a++)
        #pragma unroll
        for (int ni = 0; ni < 4; ni++)
            #pragma unroll
            for (int j = 0; j < 4; j++) acc[a][ni][j] = 0ull;

    const int kbase = sblk * KEYS_PER_BLOCK;
    const size_t vrow_base = ((size_t)b * SKK) * (HH * DD) + (size_t)h * DD;
    const size_t krow_base = (size_t)b * SKK * HH + h;

    for (int c = 0; c < KEYS_PER_BLOCK / CHUNK; c++) {
        __syncthreads();
        const int kk0 = kbase + c * CHUNK;

        // stage value rows: 32 rows x 16 float4 = 512 float4 / 256 threads
        #pragma unroll
        for (int i = 0; i < 2; i++) {
            int idx4 = i * 256 + tid;
            int k = idx4 >> 4, j = idx4 & 15;
            const float4* gp = reinterpret_cast<const float4*>(
                value + vrow_base + (size_t)(kk0 + k) * (HH * DD)) + j;
            *reinterpret_cast<float4*>(&sv[k][j * 4]) = *gp;
        }
        // trig: thread (r = tid>>5, k = tid&31) computes n = 4r..4r+3 by rotation
        {
            int r = tid >> 5;
            int k = tid & 31;
            float kv = key[krow_base + (size_t)(kk0 + k) * HH];
            float base = OMEGA() * kv;
            float s1, c1; sincosf(base, &s1, &c1);
            float sb, cb; sincosf((float)(4 * r) * base, &sb, &cb);
            #pragma unroll
            for (int j = 0; j < 4; j++) {
                scs[k][4 * r + j] = make_float2(cb, sb);
                float cn = cb * c1 - sb * s1;
                float sn = sb * c1 + cb * s1;
                cb = cn; sb = sn;
            }
        }
        __syncthreads();

        const int kb = ss * 8;
        #pragma unroll
        for (int kk = 0; kk < 8; kk++) {
            const float* vrow = &sv[kb + kk][0];
            u64 v0 = lds64(vrow + d0);
            u64 v1 = lds64(vrow + d0 + 2);
            u64 v2 = lds64(vrow + d0 + 32);
            u64 v3 = lds64(vrow + d0 + 34);
            #pragma unroll
            for (int ni = 0; ni < 4; ni++) {
                float2 tt = scs[kb + kk][n0 + ni * 8];
                u64 cc = pack2(tt.x, tt.x);
                u64 sp = pack2(tt.y, tt.y);
                acc[0][ni][0] = ffma2(cc, v0, acc[0][ni][0]);
                acc[0][ni][1] = ffma2(cc, v1, acc[0][ni][1]);
                acc[0][ni][2] = ffma2(cc, v2, acc[0][ni][2]);
                acc[0][ni][3] = ffma2(cc, v3, acc[0][ni][3]);
                acc[1][ni][0] = ffma2(sp, v0, acc[1][ni][0]);
                acc[1][ni][1] = ffma2(sp, v1, acc[1][ni][1]);
                acc[1][ni][2] = ffma2(sp, v2, acc[1][ni][2]);
                acc[1][ni][3] = ffma2(sp, v3, acc[1][ni][3]);
            }
        }
    }

    // cross-substream reduction through smem (sequential passes)
    for (int pass = 0; pass < 4; pass++) {
        __syncthreads();
        if (ss == pass) {
            #pragma unroll
            for (int ni = 0; ni < 4; ni++) {
                int fc = n0 + ni * 8;      // cos row
                int fs = 32 + fc;          // sin row
                float o[8];
                #pragma unroll
                for (int j = 0; j < 4; j++) unpack2(acc[0][ni][j], o[2*j], o[2*j+1]);
                float* pc = &red[fc][d0];
                if (pass == 0) {
                    pc[0]=o[0]; pc[1]=o[1]; pc[2]=o[2]; pc[3]=o[3];
                    pc[32]=o[4]; pc[33]=o[5]; pc[34]=o[6]; pc[35]=o[7];
                } else {
                    pc[0]+=o[0]; pc[1]+=o[1]; pc[2]+=o[2]; pc[3]+=o[3];
                    pc[32]+=o[4]; pc[33]+=o[5]; pc[34]+=o[6]; pc[35]+=o[7];
                }
                #pragma unroll
                for (int j = 0; j < 4; j++) unpack2(acc[1][ni][j], o[2*j], o[2*j+1]);
                float* ps = &red[fs][d0];
                if (pass == 0) {
                    ps[0]=o[0]; ps[1]=o[1]; ps[2]=o[2]; ps[3]=o[3];
                    ps[32]=o[4]; ps[33]=o[5]; ps[34]=o[6]; ps[35]=o[7];
                } else {
                    ps[0]+=o[0]; ps[1]+=o[1]; ps[2]+=o[2]; ps[3]+=o[3];
                    ps[32]+=o[4]; ps[33]+=o[5]; ps[34]+=o[6]; ps[35]+=o[7];
                }
            }
        }
    }
    __syncthreads();

    // write 64x64 partial tile
    float* base = g_part + (size_t)(sblk * 64 + hb) * 64 * DD;
    #pragma unroll
    for (int i = 0; i < 4; i++) {
        int idx4 = i * 256 + tid;          // 0..1023
        int f = idx4 >> 4, j = idx4 & 15;
        reinterpret_cast<float4*>(base)[idx4] =
            *reinterpret_cast<const float4*>(&red[f][j * 4]);
    }
}

// ============================================================================
// Kernel 2: reduce split partials and fold amplitudes:
//   A[n][d] = ra*KC - ia*KS ;  B[n][d] = ra*KS + ia*KC
// ============================================================================
__global__ __launch_bounds__(256) void kv_combine(const float* __restrict__ ra,
                                                  const float* __restrict__ ia) {
    const int hb = blockIdx.x;
    const int h  = hb >> 2;
    const int tid = threadIdx.x;

    #pragma unroll
    for (int i = 0; i < 8; i++) {
        int idx = i * 256 + tid;          // (n,d)
        int n = idx >> 6, d = idx & 63;
        float sc = 0.f, ss = 0.f;
        #pragma unroll
        for (int s = 0; s < SPLIT; s++) {
            const float* base = g_part + (size_t)(s * 64 + hb) * 64 * DD;
            sc += base[n * DD + d];
            ss += base[(32 + n) * DD + d];
        }
        float r  = ra[h * NN + n];
        float im = ia[h * NN + n];
        g_ab[((size_t)hb * 64 + n) * DD + d]      = r * sc - im * ss;
        g_ab[((size_t)hb * 64 + 32 + n) * DD + d] = r * ss + im * sc;
    }
}

// ============================================================================
// Kernel 3: out[q][d] = sum_n cos_q*A[n][d] + sin_q*B[n][d].
// grid: (SQ/128, 64 hb), block 128. Thread tile: 8 q x 8 d.
// ============================================================================
__global__ __launch_bounds__(128, 4) void phase2(const float* __restrict__ query,
                                                 float* __restrict__ out) {
    const int qt = blockIdx.x;
    const int hb = blockIdx.y;
    const int h  = hb >> 2;
    const int b  = hb & 3;
    const int tid = threadIdx.x;
    const int qblk = qt * 128;

    __shared__ float  sAB[64][64];      // 16 KB (A rows 0..31, B rows 32..63)
    __shared__ float2 strig[NN][128];   // 32 KB [n][q]{cos,sin}

    // load A/B tile: 1024 float4 / 128 threads = 8 each
    #pragma unroll
    for (int i = 0; i < 8; i++) {
        int idx4 = i * 128 + tid;
        reinterpret_cast<float4*>(&sAB[0][0])[idx4] =
            reinterpret_cast<const float4*>(g_ab + (size_t)hb * 64 * DD)[idx4];
    }
    // trig by rotation: thread owns one q, all 32 n
    {
        int q = tid;
        float qv = query[((size_t)b * SQQ + qblk + q) * HH + h];
        float base = OMEGA() * qv;
        float s1, c1; sincosf(base, &s1, &c1);
        float cb = 1.0f, sb = 0.0f;
        #pragma unroll
        for (int n = 0; n < NN; n++) {
            strig[n][q] = make_float2(cb, sb);
            float cn = cb * c1 - sb * s1;
            float sn = sb * c1 + cb * s1;
            cb = cn; sb = sn;
        }
    }
    __syncthreads();

    const int qg = tid >> 3;   const int q0 = qg * 8;   // 8 q
    const int dg = tid & 7;    const int d0 = dg * 4;   // 8 d (two windows)

    u64 acc[8][4];
    #pragma unroll
    for (int qi = 0; qi < 8; qi++)
        #pragma unroll
        for (int j = 0; j < 4; j++) acc[qi][j] = 0ull;

    #pragma unroll 2
    for (int n = 0; n < NN; n++) {
        const float* arow = &sAB[n][0];
        const float* brow = &sAB[32 + n][0];
        u64 a0 = lds64(arow + d0),      a1 = lds64(arow + d0 + 2);
        u64 a2 = lds64(arow + d0 + 32), a3 = lds64(arow + d0 + 34);
        u64 b0 = lds64(brow + d0),      b1 = lds64(brow + d0 + 2);
        u64 b2 = lds64(brow + d0 + 32), b3 = lds64(brow + d0 + 34);
        #pragma unroll
        for (int qi = 0; qi < 8; qi++) {
            float2 t = strig[n][q0 + qi];
            u64 cq = pack2(t.x, t.x);
            u64 sq = pack2(t.y, t.y);
            acc[qi][0] = ffma2(cq, a0, acc[qi][0]);
            acc[qi][1] = ffma2(cq, a1, acc[qi][1]);
            acc[qi][2] = ffma2(cq, a2, acc[qi][2]);
            acc[qi][3] = ffma2(cq, a3, acc[qi][3]);
            acc[qi][0] = ffma2(sq, b0, acc[qi][0]);
            acc[qi][1] = ffma2(sq, b1, acc[qi][1]);
            acc[qi][2] = ffma2(sq, b2, acc[qi][2]);
            acc[qi][3] = ffma2(sq, b3, acc[qi][3]);
        }
    }

    #pragma unroll
    for (int qi = 0; qi < 8; qi++) {
        float o[8];
        #pragma unroll
        for (int j = 0; j < 4; j++) unpack2(acc[qi][j], o[2*j], o[2*j+1]);
        float* p = out + (((size_t)b * SQQ + qblk + q0 + qi) * HH + h) * DD + d0;
        *reinterpret_cast<float4*>(p)      = make_float4(o[0], o[1], o[2], o[3]);
        *reinterpret_cast<float4*>(p + 32) = make_float4(o[4], o[5], o[6], o[7]);
    }
}

// ============================================================================
extern "C" void kernel_launch(void* const* d_in, const int* in_sizes, int n_in,
                              void* d_out, int out_size) {
    const float* key   = (const float*)d_in[0];  // (B, SK, H)
    const float* value = (const float*)d_in[1];  // (B, SK, H*D)
    const float* query = (const float*)d_in[2];  // (B, SQ, H)
    const float* ra    = (const float*)d_in[3];  // (H,1,1,N)
    const float* ia    = (const float*)d_in[4];  // (H,1,1,N)
    float* out = (float*)d_out;                  // (B, SQ, H*D)

    dim3 g1(SPLIT, 64);
    kv_partial<<<g1, 256>>>(key, value);
    kv_combine<<<64, 256>>>(ra, ia);
    dim3 g3(SQQ / 128, 64);
    phase2<<<g3, 128>>>(query, out);
}